// round 5
// baseline (speedup 1.0000x reference)
#include <cuda_runtime.h>

// NutritionLoss: reference's Gaussian soft-lookup exp(-(id-n)^2/0.01) over
// NF=1000 foods is a numerically-exact one-hot for integer ids (off-by-one
// weight = exp(-100) ~ 3.7e-44). Collapse to a hard gather from the
// nutrition table, then per-(batch,category) signed reduction, abs, scalar sum.
//
//   loss = 5 * mean_b sum_c | sum_{d,m,s} (data[pid,c]*pamt - data[tid,c]*tamt) / 700 |

#define NF 1000
#define NC 5
#define ELEMS 448   // D*M*S = 7*4*16
#define BATCH 64
#define NWARPS 14   // 448 / 32

__global__ void nl_init_out(float* __restrict__ out) {
    out[0] = 0.0f;
}

__global__ __launch_bounds__(ELEMS) void nl_main(
    const float* __restrict__ y_pred,   // [B,D,M,S,2] interleaved (id, amt)
    const float* __restrict__ y,        // [B,D,M,S,2]
    const float* __restrict__ data,     // [NF,NC]
    float* __restrict__ out)            // scalar
{
    __shared__ float sdata[NF * NC];            // 20 KB nutrition table
    __shared__ double swarp[NWARPS][NC];
    __shared__ double scat[NC];

    const int t = threadIdx.x;
    const int b = blockIdx.x;

    // Stage the table into shared memory (L2-resident after first wave).
    #pragma unroll 4
    for (int i = t; i < NF * NC; i += ELEMS) sdata[i] = data[i];
    __syncthreads();

    // One (d,m,s) slot per thread; (id, amt) pairs are interleaved -> float2.
    const float2 yp = reinterpret_cast<const float2*>(y_pred)[b * ELEMS + t];
    const float2 yt = reinterpret_cast<const float2*>(y)[b * ELEMS + t];

    const int pid = __float2int_rn(yp.x);   // matches jnp.round (no .5 cases)
    const int tid = __float2int_rn(yt.x);   // true ids are exact integers
    const float pamt = yp.y;
    const float tamt = yt.y;

    const float* __restrict__ prow = &sdata[pid * NC];
    const float* __restrict__ trow = &sdata[tid * NC];

    double acc[NC];
    #pragma unroll
    for (int c = 0; c < NC; c++)
        acc[c] = (double)prow[c] * (double)pamt - (double)trow[c] * (double)tamt;

    // Warp-level reduction of the 5 signed category sums.
    const unsigned mask = 0xffffffffu;   // 448 = 14 full warps
    #pragma unroll
    for (int c = 0; c < NC; c++) {
        double v = acc[c];
        #pragma unroll
        for (int o = 16; o > 0; o >>= 1) v += __shfl_down_sync(mask, v, o);
        if ((t & 31) == 0) swarp[t >> 5][c] = v;
    }
    __syncthreads();

    // Cross-warp reduce: thread c (c<5) sums its category over 14 warps, abs.
    if (t < NC) {
        double s = 0.0;
        #pragma unroll
        for (int w = 0; w < NWARPS; w++) s += swarp[w][t];
        scat[t] = fabs(s);
    }
    __syncthreads();

    if (t == 0) {
        double s = scat[0] + scat[1] + scat[2] + scat[3] + scat[4];
        // * (1/700) elementwise factor, * (1/B) batch mean, * 5 penalty
        atomicAdd(out, (float)(s * (5.0 / (700.0 * (double)BATCH))));
    }
}

extern "C" void kernel_launch(void* const* d_in, const int* in_sizes, int n_in,
                              void* d_out, int out_size) {
    const float* y_pred = (const float*)d_in[0];
    const float* y      = (const float*)d_in[1];
    const float* data   = (const float*)d_in[2];
    float* out = (float*)d_out;

    nl_init_out<<<1, 1>>>(out);
    nl_main<<<BATCH, ELEMS>>>(y_pred, y, data, out);
}